// round 1
// baseline (speedup 1.0000x reference)
#include <cuda_runtime.h>

#define NN 20000
#define EE 320000

constexpr size_t S_NN   = (size_t)NN * 128;            // 2.56M floats per node-feature array
constexpr size_t OFF_Q    = 0;                         // q_a, q_b            : 2*S_NN
constexpr size_t OFF_KB   = OFF_Q   + 2 * S_NN;        // k base (a,b)        : 2*S_NN
constexpr size_t OFF_VB   = OFF_KB  + 2 * S_NN;        // v base (a,b)        : 2*S_NN
constexpr size_t OFF_K    = OFF_VB  + 2 * S_NN;        // k per relation      : 4*S_NN
constexpr size_t OFF_V    = OFF_K   + 4 * S_NN;        // v per relation      : 4*S_NN
constexpr size_t OFF_EX   = OFF_V   + 4 * S_NN;        // exp(score) [4][E][8]
constexpr size_t OFF_SSUM = OFF_EX  + (size_t)4 * EE * 8;  // softmax sums [4][N][8]
constexpr size_t OFF_AGG  = OFF_SSUM+ (size_t)4 * NN * 8;  // aggregates (a,b)  : 2*S_NN
constexpr size_t TOTAL    = OFF_AGG + 2 * S_NN;

__device__ __align__(256) float g_s[TOTAL];

struct Edges { const int* src[4]; const int* dst[4]; };

// ---------------------------------------------------------------------------
// Generic (M x 128) @ (128 x 128) + bias GEMM, 128x128 block tile, 8x8 micro.
// mode 0: C = A@W + bias
// mode 1: al = sigmoid(skip[sidx]); C = al*(0.5*A@W + bias) + (1-al)*hres
// ---------------------------------------------------------------------------
__global__ __launch_bounds__(256) void gemm128(
    const float* __restrict__ A, const float* __restrict__ W,
    const float* __restrict__ bias, float* __restrict__ C, int M, int mode,
    const float* __restrict__ hres, const float* __restrict__ skip, int sidx)
{
    __shared__ float Asm[16][128];
    __shared__ float Bsm[16][128];
    int t  = threadIdx.x;
    int m0 = blockIdx.x * 128;
    int ty = t >> 4, tx = t & 15;
    float acc[8][8];
#pragma unroll
    for (int i = 0; i < 8; i++)
#pragma unroll
        for (int j = 0; j < 8; j++) acc[i][j] = 0.f;

    for (int kk = 0; kk < 128; kk += 16) {
#pragma unroll
        for (int it = 0; it < 2; it++) {
            int li = t * 2 + it;
            int m  = li >> 2;
            int k4 = (li & 3) * 4;
            float4 va;
            if (m0 + m < M) va = *(const float4*)&A[(size_t)(m0 + m) * 128 + kk + k4];
            else            va = make_float4(0.f, 0.f, 0.f, 0.f);
            Asm[k4 + 0][m] = va.x; Asm[k4 + 1][m] = va.y;
            Asm[k4 + 2][m] = va.z; Asm[k4 + 3][m] = va.w;
        }
#pragma unroll
        for (int it = 0; it < 2; it++) {
            int li = t * 2 + it;
            int k  = li >> 5;
            int n4 = (li & 31) * 4;
            *(float4*)&Bsm[k][n4] = *(const float4*)&W[(size_t)(kk + k) * 128 + n4];
        }
        __syncthreads();
#pragma unroll
        for (int k = 0; k < 16; k++) {
            float a[8], b[8];
            *(float4*)&a[0] = *(const float4*)&Asm[k][ty * 8];
            *(float4*)&a[4] = *(const float4*)&Asm[k][ty * 8 + 4];
            *(float4*)&b[0] = *(const float4*)&Bsm[k][tx * 8];
            *(float4*)&b[4] = *(const float4*)&Bsm[k][tx * 8 + 4];
#pragma unroll
            for (int i = 0; i < 8; i++)
#pragma unroll
                for (int j = 0; j < 8; j++) acc[i][j] = fmaf(a[i], b[j], acc[i][j]);
        }
        __syncthreads();
    }

    float al = 0.f, om = 0.f;
    if (mode == 1) { al = 1.f / (1.f + __expf(-skip[sidx])); om = 1.f - al; }
#pragma unroll
    for (int i = 0; i < 8; i++) {
        int row = m0 + ty * 8 + i;
        if (row >= M) continue;
#pragma unroll
        for (int j = 0; j < 8; j++) {
            int col = tx * 8 + j;
            float v = acc[i][j];
            float o;
            if (mode == 0) o = v + bias[col];
            else o = al * (0.5f * v + bias[col]) + om * hres[(size_t)row * 128 + col];
            C[(size_t)row * 128 + col] = o;
        }
    }
}

// ---------------------------------------------------------------------------
// Per-head 16x16 relation transform: out[n,h,:] = base[st][n,h,:] @ rel[r,h]
// grid: (N/2, 4 relations, 2 {k=att, v=msg}); block 256 = 2 nodes x 128 outputs
// ---------------------------------------------------------------------------
__global__ __launch_bounds__(256) void transform_kernel(
    const float* __restrict__ ratt, const float* __restrict__ rmsg)
{
    int r     = blockIdx.y;
    int which = blockIdx.z;  // 0 = k (rel_att), 1 = v (rel_msg)
    const float* rel = which ? rmsg : ratt;
    __shared__ float att_s[2048];
    for (int i = threadIdx.x; i < 2048; i += 256) att_s[i] = rel[r * 2048 + i];
    __syncthreads();

    int st = (r < 2) ? 0 : 1;  // source node type
    int n  = blockIdx.x * 2 + (threadIdx.x >> 7);
    int o  = threadIdx.x & 127;
    int h  = o >> 4, e = o & 15;

    size_t srcOff = (which ? OFF_VB : OFF_KB) + ((size_t)st * NN + n) * 128 + h * 16;
    const float4* bp = (const float4*)&g_s[srcOff];
    float acc = 0.f;
#pragma unroll
    for (int d4 = 0; d4 < 4; d4++) {
        float4 kv = bp[d4];
        int ab = (h * 16 + d4 * 4) * 16 + e;
        acc = fmaf(kv.x, att_s[ab],      acc);
        acc = fmaf(kv.y, att_s[ab + 16], acc);
        acc = fmaf(kv.z, att_s[ab + 32], acc);
        acc = fmaf(kv.w, att_s[ab + 48], acc);
    }
    g_s[(which ? OFF_V : OFF_K) + ((size_t)r * NN + n) * 128 + o] = acc;
}

// ---------------------------------------------------------------------------
// Edge scores: 1 thread per (edge, head). ex = exp(q[dst].k[src] * pri / 4)
// (max-subtraction omitted: mathematically identical softmax, scores O(1))
// ---------------------------------------------------------------------------
__global__ __launch_bounds__(256) void score_kernel(Edges eg, const float* __restrict__ pri)
{
    int r   = blockIdx.y;
    int idx = blockIdx.x * 256 + threadIdx.x;  // E*8 = 2.56M, divisible by 256
    int e = idx >> 3, h = idx & 7;
    int s = eg.src[r][e];
    int d = eg.dst[r][e];
    int dt = r & 1;  // dst node type
    const float4* qp = (const float4*)&g_s[OFF_Q + ((size_t)dt * NN + d) * 128 + h * 16];
    const float4* kp = (const float4*)&g_s[OFF_K + ((size_t)r  * NN + s) * 128 + h * 16];
    float acc = 0.f;
#pragma unroll
    for (int i = 0; i < 4; i++) {
        float4 a = qp[i], b = kp[i];
        acc += a.x * b.x + a.y * b.y + a.z * b.z + a.w * b.w;
    }
    float ex = __expf(acc * pri[r * 8 + h] * 0.25f);
    g_s[OFF_EX + ((size_t)r * EE + e) * 8 + h] = ex;
    atomicAdd(&g_s[OFF_SSUM + ((size_t)r * NN + d) * 8 + h], ex);
}

// ---------------------------------------------------------------------------
// Weighted scatter-aggregate: 32 threads per edge, vector red into agg[dst]
// ---------------------------------------------------------------------------
__global__ __launch_bounds__(256) void agg_kernel(Edges eg)
{
    int r   = blockIdx.y;
    int idx = blockIdx.x * 256 + threadIdx.x;  // E*32 = 10.24M, divisible by 256
    int e = idx >> 5, t32 = idx & 31;
    int h = t32 >> 2;
    int s = eg.src[r][e];
    int d = eg.dst[r][e];
    int dt = r & 1;
    float ex   = g_s[OFF_EX   + ((size_t)r * EE + e) * 8 + h];
    float ssum = g_s[OFF_SSUM + ((size_t)r * NN + d) * 8 + h];
    float attn = ex / ssum;
    float4 vv = *(const float4*)&g_s[OFF_V + ((size_t)r * NN + s) * 128 + t32 * 4];
    float* ap = &g_s[OFF_AGG + ((size_t)dt * NN + d) * 128 + t32 * 4];
    asm volatile("red.global.add.v4.f32 [%0], {%1,%2,%3,%4};"
                 :: "l"(ap), "f"(vv.x * attn), "f"(vv.y * attn),
                    "f"(vv.z * attn), "f"(vv.w * attn)
                 : "memory");
}

// ---------------------------------------------------------------------------
extern "C" void kernel_launch(void* const* d_in, const int* in_sizes, int n_in,
                              void* d_out, int out_size)
{
    const float* h_a  = (const float*)d_in[0];
    const float* h_b  = (const float*)d_in[1];
    const float* Wk   = (const float*)d_in[2];
    const float* bk   = (const float*)d_in[3];
    const float* Wq   = (const float*)d_in[4];
    const float* bq   = (const float*)d_in[5];
    const float* Wv   = (const float*)d_in[6];
    const float* bv   = (const float*)d_in[7];
    const float* Wa   = (const float*)d_in[8];
    const float* ba   = (const float*)d_in[9];
    const float* ratt = (const float*)d_in[10];
    const float* rmsg = (const float*)d_in[11];
    const float* rpri = (const float*)d_in[12];
    const float* skip = (const float*)d_in[13];
    float* out = (float*)d_out;

    float* base = nullptr;
    cudaGetSymbolAddress((void**)&base, g_s);

    // zero softmax sums + aggregates (contiguous region)
    cudaMemsetAsync(base + OFF_SSUM, 0,
                    ((size_t)4 * NN * 8 + 2 * S_NN) * sizeof(float));

    const int gM = (NN + 127) / 128;  // 157 blocks

    // base projections: q_a, q_b, k_a, k_b, v_a, v_b
    gemm128<<<gM, 256>>>(h_a, Wq,             bq,       base + OFF_Q,          NN, 0, nullptr, nullptr, 0);
    gemm128<<<gM, 256>>>(h_b, Wq + 128 * 128, bq + 128, base + OFF_Q + S_NN,   NN, 0, nullptr, nullptr, 0);
    gemm128<<<gM, 256>>>(h_a, Wk,             bk,       base + OFF_KB,         NN, 0, nullptr, nullptr, 0);
    gemm128<<<gM, 256>>>(h_b, Wk + 128 * 128, bk + 128, base + OFF_KB + S_NN,  NN, 0, nullptr, nullptr, 0);
    gemm128<<<gM, 256>>>(h_a, Wv,             bv,       base + OFF_VB,         NN, 0, nullptr, nullptr, 0);
    gemm128<<<gM, 256>>>(h_b, Wv + 128 * 128, bv + 128, base + OFF_VB + S_NN,  NN, 0, nullptr, nullptr, 0);

    // per-relation head transforms (rel_att for k, rel_msg for v)
    dim3 tgrid(NN / 2, 4, 2);
    transform_kernel<<<tgrid, 256>>>(ratt, rmsg);

    Edges eg;
    eg.src[0] = (const int*)d_in[14]; eg.dst[0] = (const int*)d_in[15];
    eg.src[1] = (const int*)d_in[16]; eg.dst[1] = (const int*)d_in[17];
    eg.src[2] = (const int*)d_in[18]; eg.dst[2] = (const int*)d_in[19];
    eg.src[3] = (const int*)d_in[20]; eg.dst[3] = (const int*)d_in[21];

    dim3 sgrid((EE * 8) / 256, 4);
    score_kernel<<<sgrid, 256>>>(eg, rpri);

    dim3 agrid((EE * 32) / 256, 4);
    agg_kernel<<<agrid, 256>>>(eg);

    // output GEMMs with fused mean (0.5), bias, sigmoid skip
    gemm128<<<gM, 256>>>(base + OFF_AGG,        Wa,             ba,       out,        NN, 1, h_a, skip, 0);
    gemm128<<<gM, 256>>>(base + OFF_AGG + S_NN, Wa + 128 * 128, ba + 128, out + S_NN, NN, 1, h_b, skip, 1);
}

// round 2
// speedup vs baseline: 1.2387x; 1.2387x over previous
#include <cuda_runtime.h>

#define NN 20000
#define EE 320000

constexpr size_t S_NN   = (size_t)NN * 128;
constexpr size_t OFF_Q    = 0;                         // q_a, q_b            : 2*S_NN
constexpr size_t OFF_KB   = OFF_Q   + 2 * S_NN;        // k base (a,b)        : 2*S_NN
constexpr size_t OFF_VB   = OFF_KB  + 2 * S_NN;        // v base (a,b)        : 2*S_NN
constexpr size_t OFF_K    = OFF_VB  + 2 * S_NN;        // k per relation      : 4*S_NN
constexpr size_t OFF_V    = OFF_K   + 4 * S_NN;        // v per relation      : 4*S_NN
constexpr size_t OFF_EX   = OFF_V   + 4 * S_NN;        // exp(score) [4][E][8]
constexpr size_t OFF_SSUM = OFF_EX  + (size_t)4 * EE * 8;  // softmax sums [4][N][8]
constexpr size_t OFF_AGG  = OFF_SSUM+ (size_t)4 * NN * 8;  // aggregates (a,b)  : 2*S_NN
constexpr size_t TOTAL    = OFF_AGG + 2 * S_NN;

__device__ __align__(256) float g_s[TOTAL];

struct Edges { const int* src[4]; const int* dst[4]; };

struct GemmBatch {
    const float* A[6];
    const float* W[6];
    const float* bias[6];
    float*       C[6];
    const float* hres[6];
};

// ---------------------------------------------------------------------------
// Batched (M x 128) @ (128 x 128) + bias GEMM. 128x128 block tile, 8x8 micro.
// blockIdx.y selects the GEMM within the batch.
// mode 0: C = A@W + bias
// mode 1: al = sigmoid(skip[y]); C = al*(0.5*A@W + bias) + (1-al)*hres
// ---------------------------------------------------------------------------
__global__ __launch_bounds__(256) void gemm128(
    GemmBatch gb, int M, int mode, const float* __restrict__ skip)
{
    int b = blockIdx.y;
    const float* __restrict__ A    = gb.A[b];
    const float* __restrict__ W    = gb.W[b];
    const float* __restrict__ bias = gb.bias[b];
    float*       __restrict__ C    = gb.C[b];

    __shared__ float Asm[16][128];
    __shared__ float Bsm[16][128];
    int t  = threadIdx.x;
    int m0 = blockIdx.x * 128;
    int ty = t >> 4, tx = t & 15;
    float acc[8][8];
#pragma unroll
    for (int i = 0; i < 8; i++)
#pragma unroll
        for (int j = 0; j < 8; j++) acc[i][j] = 0.f;

    for (int kk = 0; kk < 128; kk += 16) {
#pragma unroll
        for (int it = 0; it < 2; it++) {
            int li = t * 2 + it;
            int m  = li >> 2;
            int k4 = (li & 3) * 4;
            float4 va;
            if (m0 + m < M) va = *(const float4*)&A[(size_t)(m0 + m) * 128 + kk + k4];
            else            va = make_float4(0.f, 0.f, 0.f, 0.f);
            Asm[k4 + 0][m] = va.x; Asm[k4 + 1][m] = va.y;
            Asm[k4 + 2][m] = va.z; Asm[k4 + 3][m] = va.w;
        }
#pragma unroll
        for (int it = 0; it < 2; it++) {
            int li = t * 2 + it;
            int k  = li >> 5;
            int n4 = (li & 31) * 4;
            *(float4*)&Bsm[k][n4] = *(const float4*)&W[(size_t)(kk + k) * 128 + n4];
        }
        __syncthreads();
#pragma unroll
        for (int k = 0; k < 16; k++) {
            float a[8], bb[8];
            *(float4*)&a[0]  = *(const float4*)&Asm[k][ty * 8];
            *(float4*)&a[4]  = *(const float4*)&Asm[k][ty * 8 + 4];
            *(float4*)&bb[0] = *(const float4*)&Bsm[k][tx * 8];
            *(float4*)&bb[4] = *(const float4*)&Bsm[k][tx * 8 + 4];
#pragma unroll
            for (int i = 0; i < 8; i++)
#pragma unroll
                for (int j = 0; j < 8; j++) acc[i][j] = fmaf(a[i], bb[j], acc[i][j]);
        }
        __syncthreads();
    }

    float al = 0.f, om = 0.f;
    if (mode == 1) { al = 1.f / (1.f + __expf(-skip[b])); om = 1.f - al; }
    float4 bias_lo = *(const float4*)&bias[tx * 8];
    float4 bias_hi = *(const float4*)&bias[tx * 8 + 4];
    const float* bv4 = (const float*)&bias_lo;   // [b0..b3]
    const float* bv8 = (const float*)&bias_hi;   // [b4..b7]

#pragma unroll
    for (int i = 0; i < 8; i++) {
        int row = m0 + ty * 8 + i;
        if (row >= M) continue;
        float o[8];
        if (mode == 0) {
#pragma unroll
            for (int j = 0; j < 4; j++) { o[j] = acc[i][j] + bv4[j]; o[j+4] = acc[i][j+4] + bv8[j]; }
        } else {
            const float* hr = &gb.hres[b][(size_t)row * 128 + tx * 8];
            float4 h0 = *(const float4*)&hr[0];
            float4 h1 = *(const float4*)&hr[4];
            const float* hp0 = (const float*)&h0;
            const float* hp1 = (const float*)&h1;
#pragma unroll
            for (int j = 0; j < 4; j++) {
                o[j]   = al * (0.5f * acc[i][j]   + bv4[j]) + om * hp0[j];
                o[j+4] = al * (0.5f * acc[i][j+4] + bv8[j]) + om * hp1[j];
            }
        }
        float* cp = &C[(size_t)row * 128 + tx * 8];
        *(float4*)&cp[0] = make_float4(o[0], o[1], o[2], o[3]);
        *(float4*)&cp[4] = make_float4(o[4], o[5], o[6], o[7]);
    }
}

// ---------------------------------------------------------------------------
// Per-head 16x16 relation transform: out[n,h,:] = base[st][n,h,:] @ rel[r,h]
// grid: (N/2, 4 relations, 2 {k=att, v=msg}); block 256 = 2 nodes x 128 outputs
// ---------------------------------------------------------------------------
__global__ __launch_bounds__(256) void transform_kernel(
    const float* __restrict__ ratt, const float* __restrict__ rmsg)
{
    int r     = blockIdx.y;
    int which = blockIdx.z;  // 0 = k (rel_att), 1 = v (rel_msg)
    const float* rel = which ? rmsg : ratt;
    __shared__ float att_s[2048];
    for (int i = threadIdx.x; i < 2048; i += 256) att_s[i] = rel[r * 2048 + i];
    __syncthreads();

    int st = (r < 2) ? 0 : 1;  // source node type
    int n  = blockIdx.x * 2 + (threadIdx.x >> 7);
    int o  = threadIdx.x & 127;
    int h  = o >> 4, e = o & 15;

    size_t srcOff = (which ? OFF_VB : OFF_KB) + ((size_t)st * NN + n) * 128 + h * 16;
    const float4* bp = (const float4*)&g_s[srcOff];
    float acc = 0.f;
#pragma unroll
    for (int d4 = 0; d4 < 4; d4++) {
        float4 kv = bp[d4];
        int ab = (h * 16 + d4 * 4) * 16 + e;
        acc = fmaf(kv.x, att_s[ab],      acc);
        acc = fmaf(kv.y, att_s[ab + 16], acc);
        acc = fmaf(kv.z, att_s[ab + 32], acc);
        acc = fmaf(kv.w, att_s[ab + 48], acc);
    }
    g_s[(which ? OFF_V : OFF_K) + ((size_t)r * NN + n) * 128 + o] = acc;
}

// ---------------------------------------------------------------------------
// Edge scores: 1 thread per (edge, head). ex = exp(q[dst].k[src] * pri / 4)
// ---------------------------------------------------------------------------
__global__ __launch_bounds__(256) void score_kernel(Edges eg, const float* __restrict__ pri)
{
    int r   = blockIdx.y;
    int idx = blockIdx.x * 256 + threadIdx.x;  // E*8 = 2.56M, divisible by 256
    int e = idx >> 3, h = idx & 7;
    int s = eg.src[r][e];
    int d = eg.dst[r][e];
    int dt = r & 1;  // dst node type
    const float4* qp = (const float4*)&g_s[OFF_Q + ((size_t)dt * NN + d) * 128 + h * 16];
    const float4* kp = (const float4*)&g_s[OFF_K + ((size_t)r  * NN + s) * 128 + h * 16];
    float acc = 0.f;
#pragma unroll
    for (int i = 0; i < 4; i++) {
        float4 a = qp[i], b = kp[i];
        acc += a.x * b.x + a.y * b.y + a.z * b.z + a.w * b.w;
    }
    float ex = __expf(acc * pri[r * 8 + h] * 0.25f);
    g_s[OFF_EX + ((size_t)r * EE + e) * 8 + h] = ex;
    atomicAdd(&g_s[OFF_SSUM + ((size_t)r * NN + d) * 8 + h], ex);
}

// ---------------------------------------------------------------------------
// Weighted scatter-aggregate: 32 threads per edge, vector red into agg[dst]
// ---------------------------------------------------------------------------
__global__ __launch_bounds__(256) void agg_kernel(Edges eg)
{
    int r   = blockIdx.y;
    int idx = blockIdx.x * 256 + threadIdx.x;  // E*32 = 10.24M, divisible by 256
    int e = idx >> 5, t32 = idx & 31;
    int h = t32 >> 2;
    int s = eg.src[r][e];
    int d = eg.dst[r][e];
    int dt = r & 1;
    float ex   = g_s[OFF_EX   + ((size_t)r * EE + e) * 8 + h];
    float ssum = g_s[OFF_SSUM + ((size_t)r * NN + d) * 8 + h];
    float attn = ex / ssum;
    float4 vv = *(const float4*)&g_s[OFF_V + ((size_t)r * NN + s) * 128 + t32 * 4];
    float* ap = &g_s[OFF_AGG + ((size_t)dt * NN + d) * 128 + t32 * 4];
    asm volatile("red.global.add.v4.f32 [%0], {%1,%2,%3,%4};"
                 :: "l"(ap), "f"(vv.x * attn), "f"(vv.y * attn),
                    "f"(vv.z * attn), "f"(vv.w * attn)
                 : "memory");
}

// ---------------------------------------------------------------------------
extern "C" void kernel_launch(void* const* d_in, const int* in_sizes, int n_in,
                              void* d_out, int out_size)
{
    const float* h_a  = (const float*)d_in[0];
    const float* h_b  = (const float*)d_in[1];
    const float* Wk   = (const float*)d_in[2];
    const float* bk   = (const float*)d_in[3];
    const float* Wq   = (const float*)d_in[4];
    const float* bq   = (const float*)d_in[5];
    const float* Wv   = (const float*)d_in[6];
    const float* bv   = (const float*)d_in[7];
    const float* Wa   = (const float*)d_in[8];
    const float* ba   = (const float*)d_in[9];
    const float* ratt = (const float*)d_in[10];
    const float* rmsg = (const float*)d_in[11];
    const float* rpri = (const float*)d_in[12];
    const float* skip = (const float*)d_in[13];
    float* out = (float*)d_out;

    float* base = nullptr;
    cudaGetSymbolAddress((void**)&base, g_s);

    // zero softmax sums + aggregates (contiguous region)
    cudaMemsetAsync(base + OFF_SSUM, 0,
                    ((size_t)4 * NN * 8 + 2 * S_NN) * sizeof(float));

    const int gM = (NN + 127) / 128;  // 157 blocks in x

    // --- batched base projections: q_a, q_b, k_a, k_b, v_a, v_b (one launch) ---
    GemmBatch pj;
    pj.A[0] = h_a; pj.W[0] = Wq;             pj.bias[0] = bq;       pj.C[0] = base + OFF_Q;
    pj.A[1] = h_b; pj.W[1] = Wq + 128 * 128; pj.bias[1] = bq + 128; pj.C[1] = base + OFF_Q + S_NN;
    pj.A[2] = h_a; pj.W[2] = Wk;             pj.bias[2] = bk;       pj.C[2] = base + OFF_KB;
    pj.A[3] = h_b; pj.W[3] = Wk + 128 * 128; pj.bias[3] = bk + 128; pj.C[3] = base + OFF_KB + S_NN;
    pj.A[4] = h_a; pj.W[4] = Wv;             pj.bias[4] = bv;       pj.C[4] = base + OFF_VB;
    pj.A[5] = h_b; pj.W[5] = Wv + 128 * 128; pj.bias[5] = bv + 128; pj.C[5] = base + OFF_VB + S_NN;
    for (int i = 0; i < 6; i++) pj.hres[i] = nullptr;
    gemm128<<<dim3(gM, 6), 256>>>(pj, NN, 0, nullptr);

    // per-relation head transforms (rel_att for k, rel_msg for v)
    dim3 tgrid(NN / 2, 4, 2);
    transform_kernel<<<tgrid, 256>>>(ratt, rmsg);

    Edges eg;
    eg.src[0] = (const int*)d_in[14]; eg.dst[0] = (const int*)d_in[15];
    eg.src[1] = (const int*)d_in[16]; eg.dst[1] = (const int*)d_in[17];
    eg.src[2] = (const int*)d_in[18]; eg.dst[2] = (const int*)d_in[19];
    eg.src[3] = (const int*)d_in[20]; eg.dst[3] = (const int*)d_in[21];

    dim3 sgrid((EE * 8) / 256, 4);
    score_kernel<<<sgrid, 256>>>(eg, rpri);

    dim3 agrid((EE * 32) / 256, 4);
    agg_kernel<<<agrid, 256>>>(eg);

    // --- batched output GEMMs with fused mean (0.5), bias, sigmoid skip ---
    GemmBatch og;
    og.A[0] = base + OFF_AGG;        og.W[0] = Wa;             og.bias[0] = ba;       og.C[0] = out;         og.hres[0] = h_a;
    og.A[1] = base + OFF_AGG + S_NN; og.W[1] = Wa + 128 * 128; og.bias[1] = ba + 128; og.C[1] = out + S_NN;  og.hres[1] = h_b;
    for (int i = 2; i < 6; i++) { og.A[i] = nullptr; og.W[i] = nullptr; og.bias[i] = nullptr; og.C[i] = nullptr; og.hres[i] = nullptr; }
    gemm128<<<dim3(gM, 2), 256>>>(og, NN, 1, skip);
}

// round 4
// speedup vs baseline: 2.2982x; 1.8554x over previous
#include <cuda_runtime.h>

#define NN 20000
#define EE 320000
#define PAD 20480              // padded per-relation segment count (80 * 256)
#define NSEG (4 * PAD)         // 81920 total segments

constexpr size_t S_NN   = (size_t)NN * 128;
constexpr size_t OFF_Q    = 0;                          // q_a, q_b           : 2*S_NN
constexpr size_t OFF_KB   = OFF_Q   + 2 * S_NN;         // k base (a,b)       : 2*S_NN
constexpr size_t OFF_VB   = OFF_KB  + 2 * S_NN;         // v base (a,b)       : 2*S_NN
constexpr size_t OFF_K    = OFF_VB  + 2 * S_NN;         // k per relation     : 4*S_NN
constexpr size_t OFF_V    = OFF_K   + 4 * S_NN;         // v per relation     : 4*S_NN
// int scratch (1 int per float slot)
constexpr size_t OFF_SRT  = OFF_V   + 4 * S_NN;         // sorted src ids     : 4*EE
constexpr size_t OFF_OFFS = OFF_SRT + (size_t)4 * EE;   // segment offsets    : NSEG
constexpr size_t OFF_CUR  = OFF_OFFS + NSEG;            // scatter cursors    : NSEG
constexpr size_t OFF_BLK  = OFF_CUR  + NSEG;            // block partials     : 128
constexpr size_t OFF_CNT  = OFF_BLK  + 128;             // histogram          : NSEG
constexpr size_t OFF_AGG  = OFF_CNT  + NSEG;            // aggregates (a,b)   : 2*S_NN
constexpr size_t TOTAL    = OFF_AGG + 2 * S_NN;

__device__ __align__(256) float g_s[TOTAL];

struct Edges { const int* src[4]; const int* dst[4]; };

struct GemmBatch {
    const float* A[6];
    const float* W[6];
    const float* bias[6];
    float*       C[6];
    const float* hres[6];
};

// ---------------------------------------------------------------------------
// Batched (M x 128) @ (128 x 128) + bias GEMM. 128x128 block tile, 8x8 micro.
// mode 0: C = A@W + bias
// mode 1: al = sigmoid(skip[y]); C = al*(0.5*A@W + bias) + (1-al)*hres
// ---------------------------------------------------------------------------
__global__ __launch_bounds__(256) void gemm128(
    GemmBatch gb, int M, int mode, const float* __restrict__ skip)
{
    int b = blockIdx.y;
    const float* __restrict__ A    = gb.A[b];
    const float* __restrict__ W    = gb.W[b];
    const float* __restrict__ bias = gb.bias[b];
    float*       __restrict__ C    = gb.C[b];

    __shared__ float Asm[16][128];
    __shared__ float Bsm[16][128];
    int t  = threadIdx.x;
    int m0 = blockIdx.x * 128;
    int ty = t >> 4, tx = t & 15;
    float acc[8][8];
#pragma unroll
    for (int i = 0; i < 8; i++)
#pragma unroll
        for (int j = 0; j < 8; j++) acc[i][j] = 0.f;

    for (int kk = 0; kk < 128; kk += 16) {
#pragma unroll
        for (int it = 0; it < 2; it++) {
            int li = t * 2 + it;
            int m  = li >> 2;
            int k4 = (li & 3) * 4;
            float4 va;
            if (m0 + m < M) va = *(const float4*)&A[(size_t)(m0 + m) * 128 + kk + k4];
            else            va = make_float4(0.f, 0.f, 0.f, 0.f);
            Asm[k4 + 0][m] = va.x; Asm[k4 + 1][m] = va.y;
            Asm[k4 + 2][m] = va.z; Asm[k4 + 3][m] = va.w;
        }
#pragma unroll
        for (int it = 0; it < 2; it++) {
            int li = t * 2 + it;
            int k  = li >> 5;
            int n4 = (li & 31) * 4;
            *(float4*)&Bsm[k][n4] = *(const float4*)&W[(size_t)(kk + k) * 128 + n4];
        }
        __syncthreads();
#pragma unroll
        for (int k = 0; k < 16; k++) {
            float a[8], bb[8];
            *(float4*)&a[0]  = *(const float4*)&Asm[k][ty * 8];
            *(float4*)&a[4]  = *(const float4*)&Asm[k][ty * 8 + 4];
            *(float4*)&bb[0] = *(const float4*)&Bsm[k][tx * 8];
            *(float4*)&bb[4] = *(const float4*)&Bsm[k][tx * 8 + 4];
#pragma unroll
            for (int i = 0; i < 8; i++)
#pragma unroll
                for (int j = 0; j < 8; j++) acc[i][j] = fmaf(a[i], bb[j], acc[i][j]);
        }
        __syncthreads();
    }

    float al = 0.f, om = 0.f;
    if (mode == 1) { al = 1.f / (1.f + __expf(-skip[b])); om = 1.f - al; }
    float4 bias_lo = *(const float4*)&bias[tx * 8];
    float4 bias_hi = *(const float4*)&bias[tx * 8 + 4];
    const float* bv4 = (const float*)&bias_lo;
    const float* bv8 = (const float*)&bias_hi;

#pragma unroll
    for (int i = 0; i < 8; i++) {
        int row = m0 + ty * 8 + i;
        if (row >= M) continue;
        float o[8];
        if (mode == 0) {
#pragma unroll
            for (int j = 0; j < 4; j++) { o[j] = acc[i][j] + bv4[j]; o[j+4] = acc[i][j+4] + bv8[j]; }
        } else {
            const float* hr = &gb.hres[b][(size_t)row * 128 + tx * 8];
            float4 h0 = *(const float4*)&hr[0];
            float4 h1 = *(const float4*)&hr[4];
            const float* hp0 = (const float*)&h0;
            const float* hp1 = (const float*)&h1;
#pragma unroll
            for (int j = 0; j < 4; j++) {
                o[j]   = al * (0.5f * acc[i][j]   + bv4[j]) + om * hp0[j];
                o[j+4] = al * (0.5f * acc[i][j+4] + bv8[j]) + om * hp1[j];
            }
        }
        float* cp = &C[(size_t)row * 128 + tx * 8];
        *(float4*)&cp[0] = make_float4(o[0], o[1], o[2], o[3]);
        *(float4*)&cp[4] = make_float4(o[4], o[5], o[6], o[7]);
    }
}

// ---------------------------------------------------------------------------
// Per-head 16x16 relation transform: out[n,h,:] = base[st][n,h,:] @ rel[r,h]
// ---------------------------------------------------------------------------
__global__ __launch_bounds__(256) void transform_kernel(
    const float* __restrict__ ratt, const float* __restrict__ rmsg)
{
    int r     = blockIdx.y;
    int which = blockIdx.z;  // 0 = k (rel_att), 1 = v (rel_msg)
    const float* rel = which ? rmsg : ratt;
    __shared__ float att_s[2048];
    for (int i = threadIdx.x; i < 2048; i += 256) att_s[i] = rel[r * 2048 + i];
    __syncthreads();

    int st = (r < 2) ? 0 : 1;
    int n  = blockIdx.x * 2 + (threadIdx.x >> 7);
    int o  = threadIdx.x & 127;
    int h  = o >> 4, e = o & 15;

    size_t srcOff = (which ? OFF_VB : OFF_KB) + ((size_t)st * NN + n) * 128 + h * 16;
    const float4* bp = (const float4*)&g_s[srcOff];
    float acc = 0.f;
#pragma unroll
    for (int d4 = 0; d4 < 4; d4++) {
        float4 kv = bp[d4];
        int ab = (h * 16 + d4 * 4) * 16 + e;
        acc = fmaf(kv.x, att_s[ab],      acc);
        acc = fmaf(kv.y, att_s[ab + 16], acc);
        acc = fmaf(kv.z, att_s[ab + 32], acc);
        acc = fmaf(kv.w, att_s[ab + 48], acc);
    }
    g_s[(which ? OFF_V : OFF_K) + ((size_t)r * NN + n) * 128 + o] = acc;
}

// ---------------------------------------------------------------------------
// Counting sort of edges by (relation, dst)
// ---------------------------------------------------------------------------
__global__ __launch_bounds__(256) void hist_kernel(Edges eg)
{
    int r = blockIdx.y;
    int e = blockIdx.x * 256 + threadIdx.x;
    int d = eg.dst[r][e];
    atomicAdd((int*)&g_s[OFF_CNT] + r * PAD + d, 1);
}

__global__ __launch_bounds__(256) void scanA_kernel()
{
    const int* cnt  = (const int*)&g_s[OFF_CNT];
    int*       offs = (int*)&g_s[OFF_OFFS];
    int*       blk  = (int*)&g_s[OFF_BLK];
    __shared__ int sm[256];
    int t = threadIdx.x;
    int base = (blockIdx.x * 256 + t) * 4;
    int c0 = cnt[base], c1 = cnt[base + 1], c2 = cnt[base + 2], c3 = cnt[base + 3];
    int tot = c0 + c1 + c2 + c3;
    sm[t] = tot;
    __syncthreads();
#pragma unroll
    for (int off = 1; off < 256; off <<= 1) {
        int u = (t >= off) ? sm[t - off] : 0;
        __syncthreads();
        sm[t] += u;
        __syncthreads();
    }
    int ex = sm[t] - tot;  // block-local exclusive prefix
    offs[base]     = ex;
    offs[base + 1] = ex + c0;
    offs[base + 2] = ex + c0 + c1;
    offs[base + 3] = ex + c0 + c1 + c2;
    if (t == 255) blk[blockIdx.x] = sm[255];
}

__global__ void scanB_kernel()
{
    int* blk = (int*)&g_s[OFF_BLK];
    __shared__ int sm[80];
    int t = threadIdx.x;
    if (t < 80) sm[t] = blk[t];
    __syncthreads();
    if (t == 0) {
        int run = 0;
#pragma unroll
        for (int i = 0; i < 80; i++) { int c = sm[i]; sm[i] = run; run += c; }
    }
    __syncthreads();
    if (t < 80) blk[t] = sm[t];
}

__global__ __launch_bounds__(256) void scanC_kernel()
{
    int* offs = (int*)&g_s[OFF_OFFS];
    int* cur  = (int*)&g_s[OFF_CUR];
    const int* blk = (const int*)&g_s[OFF_BLK];
    int i = blockIdx.x * 256 + threadIdx.x;  // NSEG threads
    int v = offs[i] + blk[i >> 10];
    offs[i] = v;
    cur[i]  = v;
}

__global__ __launch_bounds__(256) void scatter_kernel(Edges eg)
{
    int r = blockIdx.y;
    int e = blockIdx.x * 256 + threadIdx.x;
    int d = eg.dst[r][e];
    int pos = atomicAdd((int*)&g_s[OFF_CUR] + r * PAD + d, 1);
    ((int*)&g_s[OFF_SRT])[pos] = eg.src[r][e];
}

// ---------------------------------------------------------------------------
// Fused score + softmax + aggregate. One warp per (dst, relation) segment.
// acc = sum_e exp(q.k * pri/4) * v ;  ssum = sum_e exp(...) ; out += acc/ssum
// ---------------------------------------------------------------------------
__global__ __launch_bounds__(256) void attn_kernel(const float* __restrict__ pri)
{
    int warp = (blockIdx.x * 256 + threadIdx.x) >> 5;  // NSEG warps
    int lane = threadIdx.x & 31;
    int r = warp / PAD;
    int d = warp - r * PAD;
    if (d >= NN) return;
    const int* offs = (const int*)&g_s[OFF_OFFS];
    int beg = offs[warp];
    int end = offs[warp + 1];  // next entry always exists (PAD > NN)
    if (beg == end) return;

    int dt = r & 1;
    float4 q4 = *((const float4*)&g_s[OFF_Q + ((size_t)dt * NN + d) * 128] + lane);
    float ph = pri[r * 8 + (lane >> 2)] * 0.25f;

    const int*   ss    = (const int*)&g_s[OFF_SRT];
    const float* kbase = &g_s[OFF_K + (size_t)r * NN * 128];
    const float* vbase = &g_s[OFF_V + (size_t)r * NN * 128];

    float4 acc = make_float4(0.f, 0.f, 0.f, 0.f);
    float ssum = 0.f;

    for (int c = beg; c < end; c += 32) {
        int m = end - c; if (m > 32) m = 32;
        int sl = ss[c + (lane < m ? lane : m - 1)];
        int s0 = __shfl_sync(0xffffffffu, sl, 0);
        float4 k4 = *((const float4*)(kbase + (size_t)s0 * 128) + lane);
        float4 v4 = *((const float4*)(vbase + (size_t)s0 * 128) + lane);
        for (int j = 0; j < m; j++) {
            float4 ck = k4, cv = v4;
            if (j + 1 < m) {
                int s2 = __shfl_sync(0xffffffffu, sl, j + 1);
                k4 = *((const float4*)(kbase + (size_t)s2 * 128) + lane);
                v4 = *((const float4*)(vbase + (size_t)s2 * 128) + lane);
            }
            float dot = ck.x * q4.x + ck.y * q4.y + ck.z * q4.z + ck.w * q4.w;
            dot += __shfl_xor_sync(0xffffffffu, dot, 1);
            dot += __shfl_xor_sync(0xffffffffu, dot, 2);
            float exv = __expf(dot * ph);
            ssum += exv;
            acc.x = fmaf(exv, cv.x, acc.x);
            acc.y = fmaf(exv, cv.y, acc.y);
            acc.z = fmaf(exv, cv.z, acc.z);
            acc.w = fmaf(exv, cv.w, acc.w);
        }
    }

    float inv = 1.f / ssum;
    float* ap = &g_s[OFF_AGG + ((size_t)dt * NN + d) * 128] + lane * 4;
    asm volatile("red.global.add.v4.f32 [%0], {%1,%2,%3,%4};"
                 :: "l"(ap), "f"(acc.x * inv), "f"(acc.y * inv),
                    "f"(acc.z * inv), "f"(acc.w * inv)
                 : "memory");
}

// ---------------------------------------------------------------------------
extern "C" void kernel_launch(void* const* d_in, const int* in_sizes, int n_in,
                              void* d_out, int out_size)
{
    const float* h_a  = (const float*)d_in[0];
    const float* h_b  = (const float*)d_in[1];
    const float* Wk   = (const float*)d_in[2];
    const float* bk   = (const float*)d_in[3];
    const float* Wq   = (const float*)d_in[4];
    const float* bq   = (const float*)d_in[5];
    const float* Wv   = (const float*)d_in[6];
    const float* bv   = (const float*)d_in[7];
    const float* Wa   = (const float*)d_in[8];
    const float* ba   = (const float*)d_in[9];
    const float* ratt = (const float*)d_in[10];
    const float* rmsg = (const float*)d_in[11];
    const float* rpri = (const float*)d_in[12];
    const float* skip = (const float*)d_in[13];
    float* out = (float*)d_out;

    float* base = nullptr;
    cudaGetSymbolAddress((void**)&base, g_s);

    // zero histogram + aggregates (contiguous)
    cudaMemsetAsync(base + OFF_CNT, 0, ((size_t)NSEG + 2 * S_NN) * sizeof(float));

    Edges eg;
    eg.src[0] = (const int*)d_in[14]; eg.dst[0] = (const int*)d_in[15];
    eg.src[1] = (const int*)d_in[16]; eg.dst[1] = (const int*)d_in[17];
    eg.src[2] = (const int*)d_in[18]; eg.dst[2] = (const int*)d_in[19];
    eg.src[3] = (const int*)d_in[20]; eg.dst[3] = (const int*)d_in[21];

    // --- counting sort of edges by (rel, dst) ---
    dim3 egrid(EE / 256, 4);
    hist_kernel<<<egrid, 256>>>(eg);
    scanA_kernel<<<NSEG / 1024, 256>>>();
    scanB_kernel<<<1, 128>>>();
    scanC_kernel<<<NSEG / 256, 256>>>();
    scatter_kernel<<<egrid, 256>>>(eg);

    const int gM = (NN + 127) / 128;  // 157

    // --- batched base projections: q_a, q_b, k_a, k_b, v_a, v_b ---
    GemmBatch pj;
    pj.A[0] = h_a; pj.W[0] = Wq;             pj.bias[0] = bq;       pj.C[0] = base + OFF_Q;
    pj.A[1] = h_b; pj.W[1] = Wq + 128 * 128; pj.bias[1] = bq + 128; pj.C[1] = base + OFF_Q + S_NN;
    pj.A[2] = h_a; pj.W[2] = Wk;             pj.bias[2] = bk;       pj.C[2] = base + OFF_KB;
    pj.A[3] = h_b; pj.W[3] = Wk + 128 * 128; pj.bias[3] = bk + 128; pj.C[3] = base + OFF_KB + S_NN;
    pj.A[4] = h_a; pj.W[4] = Wv;             pj.bias[4] = bv;       pj.C[4] = base + OFF_VB;
    pj.A[5] = h_b; pj.W[5] = Wv + 128 * 128; pj.bias[5] = bv + 128; pj.C[5] = base + OFF_VB + S_NN;
    for (int i = 0; i < 6; i++) pj.hres[i] = nullptr;
    gemm128<<<dim3(gM, 6), 256>>>(pj, NN, 0, nullptr);

    // per-relation head transforms
    dim3 tgrid(NN / 2, 4, 2);
    transform_kernel<<<tgrid, 256>>>(ratt, rmsg);

    // --- fused score + softmax + aggregate ---
    attn_kernel<<<NSEG / 8, 256>>>(rpri);

    // --- batched output GEMMs with fused mean (0.5), bias, sigmoid skip ---
    GemmBatch og;
    og.A[0] = base + OFF_AGG;        og.W[0] = Wa;             og.bias[0] = ba;       og.C[0] = out;        og.hres[0] = h_a;
    og.A[1] = base + OFF_AGG + S_NN; og.W[1] = Wa + 128 * 128; og.bias[1] = ba + 128; og.C[1] = out + S_NN; og.hres[1] = h_b;
    for (int i = 2; i < 6; i++) { og.A[i] = nullptr; og.W[i] = nullptr; og.bias[i] = nullptr; og.C[i] = nullptr; og.hres[i] = nullptr; }
    gemm128<<<dim3(gM, 2), 256>>>(og, NN, 1, skip);
}

// round 5
// speedup vs baseline: 2.4938x; 1.0851x over previous
#include <cuda_runtime.h>

#define NN 20000
#define EE 320000
#define PAD 20480              // padded per-relation segment count (80 * 256)
#define NSEG (4 * PAD)         // 81920 total segments

constexpr size_t S_NN   = (size_t)NN * 128;
constexpr size_t OFF_Q    = 0;                          // q_a, q_b           : 2*S_NN
constexpr size_t OFF_KB   = OFF_Q   + 2 * S_NN;         // k base (a,b)       : 2*S_NN
constexpr size_t OFF_VB   = OFF_KB  + 2 * S_NN;         // v base (a,b)       : 2*S_NN
constexpr size_t OFF_K    = OFF_VB  + 2 * S_NN;         // k per relation     : 4*S_NN
constexpr size_t OFF_V    = OFF_K   + 4 * S_NN;         // v per relation     : 4*S_NN
constexpr size_t OFF_SRT  = OFF_V   + 4 * S_NN;         // sorted src ids     : 4*EE
constexpr size_t OFF_OFFS = OFF_SRT + (size_t)4 * EE;   // segment offsets    : NSEG
constexpr size_t OFF_CUR  = OFF_OFFS + NSEG;            // scatter cursors    : NSEG
constexpr size_t OFF_BLK  = OFF_CUR  + NSEG;            // block partials     : 128
constexpr size_t OFF_CNT  = OFF_BLK  + 128;             // histogram          : NSEG
constexpr size_t OFF_AGG  = OFF_CNT  + NSEG;            // aggregates (a,b)   : 2*S_NN
constexpr size_t TOTAL    = OFF_AGG + 2 * S_NN;

__device__ __align__(256) float g_s[TOTAL];

typedef unsigned long long u64;

__device__ __forceinline__ u64 pk2(float x) {
    u64 r; asm("mov.b64 %0, {%1, %1};" : "=l"(r) : "f"(x)); return r;
}
__device__ __forceinline__ void fma2(u64& d, u64 a, u64 b) {
    asm("fma.rn.f32x2 %0, %1, %2, %0;" : "+l"(d) : "l"(a), "l"(b));
}
__device__ __forceinline__ float2 up2(u64 v) {
    float2 f; asm("mov.b64 {%0, %1}, %2;" : "=f"(f.x), "=f"(f.y) : "l"(v)); return f;
}

struct Edges { const int* src[4]; const int* dst[4]; };

struct GemmBatch {
    const float* A[6];
    const float* W[6];
    const float* bias[6];
    float*       C[6];
    const float* hres[6];
};

// ---------------------------------------------------------------------------
// Batched (M x 128) @ (128 x 128) + bias GEMM. 128x128 block tile, 8x8 micro
// computed as 8 x (4 f32x2) packed FFMA2.
// mode 0: C = A@W + bias
// mode 1: al = sigmoid(skip[y]); C = al*(0.5*A@W + bias) + (1-al)*hres
// ---------------------------------------------------------------------------
__global__ __launch_bounds__(256) void gemm128(
    GemmBatch gb, int M, int mode, const float* __restrict__ skip)
{
    int b = blockIdx.y;
    const float* __restrict__ A    = gb.A[b];
    const float* __restrict__ W    = gb.W[b];
    const float* __restrict__ bias = gb.bias[b];
    float*       __restrict__ C    = gb.C[b];

    __shared__ float Asm[16][128];
    __shared__ float Bsm[16][128];
    int t  = threadIdx.x;
    int m0 = blockIdx.x * 128;
    int ty = t >> 4, tx = t & 15;
    u64 acc2[8][4];
#pragma unroll
    for (int i = 0; i < 8; i++)
#pragma unroll
        for (int j = 0; j < 4; j++) acc2[i][j] = 0ull;

    for (int kk = 0; kk < 128; kk += 16) {
#pragma unroll
        for (int it = 0; it < 2; it++) {
            int li = t * 2 + it;
            int m  = li >> 2;
            int k4 = (li & 3) * 4;
            float4 va;
            if (m0 + m < M) va = *(const float4*)&A[(size_t)(m0 + m) * 128 + kk + k4];
            else            va = make_float4(0.f, 0.f, 0.f, 0.f);
            Asm[k4 + 0][m] = va.x; Asm[k4 + 1][m] = va.y;
            Asm[k4 + 2][m] = va.z; Asm[k4 + 3][m] = va.w;
        }
#pragma unroll
        for (int it = 0; it < 2; it++) {
            int li = t * 2 + it;
            int k  = li >> 5;
            int n4 = (li & 31) * 4;
            *(float4*)&Bsm[k][n4] = *(const float4*)&W[(size_t)(kk + k) * 128 + n4];
        }
        __syncthreads();
#pragma unroll
        for (int k = 0; k < 16; k++) {
            float a[8];
            *(float4*)&a[0] = *(const float4*)&Asm[k][ty * 8];
            *(float4*)&a[4] = *(const float4*)&Asm[k][ty * 8 + 4];
            ulonglong2 p0 = *(const ulonglong2*)&Bsm[k][tx * 8];
            ulonglong2 p1 = *(const ulonglong2*)&Bsm[k][tx * 8 + 4];
#pragma unroll
            for (int i = 0; i < 8; i++) {
                u64 a2 = pk2(a[i]);
                fma2(acc2[i][0], a2, p0.x);
                fma2(acc2[i][1], a2, p0.y);
                fma2(acc2[i][2], a2, p1.x);
                fma2(acc2[i][3], a2, p1.y);
            }
        }
        __syncthreads();
    }

    float al = 0.f, om = 0.f;
    if (mode == 1) { al = 1.f / (1.f + __expf(-skip[b])); om = 1.f - al; }
    float4 bias_lo = *(const float4*)&bias[tx * 8];
    float4 bias_hi = *(const float4*)&bias[tx * 8 + 4];
    const float* bv = (const float*)&bias_lo;   // bv[0..3], then bias_hi follows
    const float* bh = (const float*)&bias_hi;

#pragma unroll
    for (int i = 0; i < 8; i++) {
        int row = m0 + ty * 8 + i;
        if (row >= M) continue;
        float v[8];
#pragma unroll
        for (int j = 0; j < 4; j++) {
            float2 p = up2(acc2[i][j]);
            v[2 * j] = p.x; v[2 * j + 1] = p.y;
        }
        float o[8];
        if (mode == 0) {
#pragma unroll
            for (int j = 0; j < 4; j++) { o[j] = v[j] + bv[j]; o[j + 4] = v[j + 4] + bh[j]; }
        } else {
            const float* hr = &gb.hres[b][(size_t)row * 128 + tx * 8];
            float4 h0 = *(const float4*)&hr[0];
            float4 h1 = *(const float4*)&hr[4];
            const float* hp0 = (const float*)&h0;
            const float* hp1 = (const float*)&h1;
#pragma unroll
            for (int j = 0; j < 4; j++) {
                o[j]     = al * (0.5f * v[j]     + bv[j]) + om * hp0[j];
                o[j + 4] = al * (0.5f * v[j + 4] + bh[j]) + om * hp1[j];
            }
        }
        float* cp = &C[(size_t)row * 128 + tx * 8];
        *(float4*)&cp[0] = make_float4(o[0], o[1], o[2], o[3]);
        *(float4*)&cp[4] = make_float4(o[4], o[5], o[6], o[7]);
    }
}

// ---------------------------------------------------------------------------
// Per-head 16x16 relation transform: out[n,h,:] = base[st][n,h,:] @ rel[r,h]
// f32x2: each thread computes an adjacent e-pair. 256 thr = 4 nodes x 64.
// ---------------------------------------------------------------------------
__global__ __launch_bounds__(256) void transform_kernel(
    const float* __restrict__ ratt, const float* __restrict__ rmsg)
{
    int r     = blockIdx.y;
    int which = blockIdx.z;  // 0 = k (rel_att), 1 = v (rel_msg)
    const float* rel = which ? rmsg : ratt;
    __shared__ float att_s[2048];
    for (int i = threadIdx.x; i < 2048; i += 256) att_s[i] = rel[r * 2048 + i];
    __syncthreads();

    int st = (r < 2) ? 0 : 1;
    int n  = blockIdx.x * 4 + (threadIdx.x >> 6);
    int o2 = threadIdx.x & 63;
    int h  = o2 >> 3, ep = (o2 & 7) * 2;

    size_t srcOff = (which ? OFF_VB : OFF_KB) + ((size_t)st * NN + n) * 128 + h * 16;
    const float4* bp = (const float4*)&g_s[srcOff];
    u64 acc = 0ull;
#pragma unroll
    for (int d4 = 0; d4 < 4; d4++) {
        float4 kv = bp[d4];
        int ab = (h * 16 + d4 * 4) * 16 + ep;
        fma2(acc, pk2(kv.x), *(const u64*)&att_s[ab]);
        fma2(acc, pk2(kv.y), *(const u64*)&att_s[ab + 16]);
        fma2(acc, pk2(kv.z), *(const u64*)&att_s[ab + 32]);
        fma2(acc, pk2(kv.w), *(const u64*)&att_s[ab + 48]);
    }
    float2 res = up2(acc);
    *(float2*)&g_s[(which ? OFF_V : OFF_K) + ((size_t)r * NN + n) * 128 + h * 16 + ep] = res;
}

// ---------------------------------------------------------------------------
// Counting sort of edges by (relation, dst)
// ---------------------------------------------------------------------------
__global__ __launch_bounds__(256) void hist_kernel(Edges eg)
{
    int r = blockIdx.y;
    int e = blockIdx.x * 256 + threadIdx.x;
    int d = eg.dst[r][e];
    atomicAdd((int*)&g_s[OFF_CNT] + r * PAD + d, 1);
}

__global__ __launch_bounds__(256) void scanA_kernel()
{
    const int* cnt  = (const int*)&g_s[OFF_CNT];
    int*       offs = (int*)&g_s[OFF_OFFS];
    int*       blk  = (int*)&g_s[OFF_BLK];
    __shared__ int sm[256];
    int t = threadIdx.x;
    int base = (blockIdx.x * 256 + t) * 4;
    int c0 = cnt[base], c1 = cnt[base + 1], c2 = cnt[base + 2], c3 = cnt[base + 3];
    int tot = c0 + c1 + c2 + c3;
    sm[t] = tot;
    __syncthreads();
#pragma unroll
    for (int off = 1; off < 256; off <<= 1) {
        int u = (t >= off) ? sm[t - off] : 0;
        __syncthreads();
        sm[t] += u;
        __syncthreads();
    }
    int ex = sm[t] - tot;  // block-local exclusive prefix
    offs[base]     = ex;
    offs[base + 1] = ex + c0;
    offs[base + 2] = ex + c0 + c1;
    offs[base + 3] = ex + c0 + c1 + c2;
    if (t == 255) blk[blockIdx.x] = sm[255];
}

__global__ void scanB_kernel()
{
    int* blk = (int*)&g_s[OFF_BLK];
    __shared__ int sm[80];
    int t = threadIdx.x;
    if (t < 80) sm[t] = blk[t];
    __syncthreads();
    if (t == 0) {
        int run = 0;
#pragma unroll
        for (int i = 0; i < 80; i++) { int c = sm[i]; sm[i] = run; run += c; }
    }
    __syncthreads();
    if (t < 80) blk[t] = sm[t];
}

__global__ __launch_bounds__(256) void scanC_kernel()
{
    int* offs = (int*)&g_s[OFF_OFFS];
    int* cur  = (int*)&g_s[OFF_CUR];
    const int* blk = (const int*)&g_s[OFF_BLK];
    int i = blockIdx.x * 256 + threadIdx.x;  // NSEG threads
    int v = offs[i] + blk[i >> 10];
    offs[i] = v;
    cur[i]  = v;
}

__global__ __launch_bounds__(256) void scatter_kernel(Edges eg)
{
    int r = blockIdx.y;
    int e = blockIdx.x * 256 + threadIdx.x;
    int d = eg.dst[r][e];
    int pos = atomicAdd((int*)&g_s[OFF_CUR] + r * PAD + d, 1);
    ((int*)&g_s[OFF_SRT])[pos] = eg.src[r][e];
}

// ---------------------------------------------------------------------------
// Fused score + softmax + aggregate. One warp per (dst-type, node) — handles
// BOTH relations targeting that node type, then a single plain STG.128.
// ---------------------------------------------------------------------------
__global__ __launch_bounds__(256) void attn_kernel(const float* __restrict__ pri)
{
    int warp = (blockIdx.x * 256 + threadIdx.x) >> 5;  // 2*PAD warps
    int lane = threadIdx.x & 31;
    int dt = warp / PAD;
    int d  = warp - dt * PAD;
    if (d >= NN) return;
    const int* offs = (const int*)&g_s[OFF_OFFS];
    const int* ss   = (const int*)&g_s[OFF_SRT];

    float4 q4 = *((const float4*)&g_s[OFF_Q + ((size_t)dt * NN + d) * 128] + lane);
    float4 tot = make_float4(0.f, 0.f, 0.f, 0.f);

#pragma unroll
    for (int half = 0; half < 2; half++) {
        int r   = dt + half * 2;
        int seg = r * PAD + d;
        int beg = offs[seg];
        int end = offs[seg + 1];
        if (beg == end) continue;

        float ph = pri[r * 8 + (lane >> 2)] * 0.25f;
        const float* kbase = &g_s[OFF_K + (size_t)r * NN * 128];
        const float* vbase = &g_s[OFF_V + (size_t)r * NN * 128];

        float4 acc = make_float4(0.f, 0.f, 0.f, 0.f);
        float ssum = 0.f;

        for (int c = beg; c < end; c += 32) {
            int m = end - c; if (m > 32) m = 32;
            int sl = ss[c + (lane < m ? lane : m - 1)];
            int s0 = __shfl_sync(0xffffffffu, sl, 0);
            float4 k4 = *((const float4*)(kbase + (size_t)s0 * 128) + lane);
            float4 v4 = *((const float4*)(vbase + (size_t)s0 * 128) + lane);
            for (int j = 0; j < m; j++) {
                float4 ck = k4, cv = v4;
                if (j + 1 < m) {
                    int s2 = __shfl_sync(0xffffffffu, sl, j + 1);
                    k4 = *((const float4*)(kbase + (size_t)s2 * 128) + lane);
                    v4 = *((const float4*)(vbase + (size_t)s2 * 128) + lane);
                }
                float dot = ck.x * q4.x + ck.y * q4.y + ck.z * q4.z + ck.w * q4.w;
                dot += __shfl_xor_sync(0xffffffffu, dot, 1);
                dot += __shfl_xor_sync(0xffffffffu, dot, 2);
                float exv = __expf(dot * ph);
                ssum += exv;
                acc.x = fmaf(exv, cv.x, acc.x);
                acc.y = fmaf(exv, cv.y, acc.y);
                acc.z = fmaf(exv, cv.z, acc.z);
                acc.w = fmaf(exv, cv.w, acc.w);
            }
        }
        float inv = 1.f / ssum;
        tot.x = fmaf(acc.x, inv, tot.x);
        tot.y = fmaf(acc.y, inv, tot.y);
        tot.z = fmaf(acc.z, inv, tot.z);
        tot.w = fmaf(acc.w, inv, tot.w);
    }

    *(float4*)(&g_s[OFF_AGG + ((size_t)dt * NN + d) * 128] + lane * 4) = tot;
}

// ---------------------------------------------------------------------------
extern "C" void kernel_launch(void* const* d_in, const int* in_sizes, int n_in,
                              void* d_out, int out_size)
{
    const float* h_a  = (const float*)d_in[0];
    const float* h_b  = (const float*)d_in[1];
    const float* Wk   = (const float*)d_in[2];
    const float* bk   = (const float*)d_in[3];
    const float* Wq   = (const float*)d_in[4];
    const float* bq   = (const float*)d_in[5];
    const float* Wv   = (const float*)d_in[6];
    const float* bv   = (const float*)d_in[7];
    const float* Wa   = (const float*)d_in[8];
    const float* ba   = (const float*)d_in[9];
    const float* ratt = (const float*)d_in[10];
    const float* rmsg = (const float*)d_in[11];
    const float* rpri = (const float*)d_in[12];
    const float* skip = (const float*)d_in[13];
    float* out = (float*)d_out;

    float* base = nullptr;
    cudaGetSymbolAddress((void**)&base, g_s);

    // zero only the histogram (agg no longer needs zeroing — plain stores)
    cudaMemsetAsync(base + OFF_CNT, 0, (size_t)NSEG * sizeof(int));

    Edges eg;
    eg.src[0] = (const int*)d_in[14]; eg.dst[0] = (const int*)d_in[15];
    eg.src[1] = (const int*)d_in[16]; eg.dst[1] = (const int*)d_in[17];
    eg.src[2] = (const int*)d_in[18]; eg.dst[2] = (const int*)d_in[19];
    eg.src[3] = (const int*)d_in[20]; eg.dst[3] = (const int*)d_in[21];

    // --- counting sort of edges by (rel, dst) ---
    dim3 egrid(EE / 256, 4);
    hist_kernel<<<egrid, 256>>>(eg);
    scanA_kernel<<<NSEG / 1024, 256>>>();
    scanB_kernel<<<1, 128>>>();
    scanC_kernel<<<NSEG / 256, 256>>>();
    scatter_kernel<<<egrid, 256>>>(eg);

    const int gM = (NN + 127) / 128;  // 157

    // --- batched base projections: q_a, q_b, k_a, k_b, v_a, v_b ---
    GemmBatch pj;
    pj.A[0] = h_a; pj.W[0] = Wq;             pj.bias[0] = bq;       pj.C[0] = base + OFF_Q;
    pj.A[1] = h_b; pj.W[1] = Wq + 128 * 128; pj.bias[1] = bq + 128; pj.C[1] = base + OFF_Q + S_NN;
    pj.A[2] = h_a; pj.W[2] = Wk;             pj.bias[2] = bk;       pj.C[2] = base + OFF_KB;
    pj.A[3] = h_b; pj.W[3] = Wk + 128 * 128; pj.bias[3] = bk + 128; pj.C[3] = base + OFF_KB + S_NN;
    pj.A[4] = h_a; pj.W[4] = Wv;             pj.bias[4] = bv;       pj.C[4] = base + OFF_VB;
    pj.A[5] = h_b; pj.W[5] = Wv + 128 * 128; pj.bias[5] = bv + 128; pj.C[5] = base + OFF_VB + S_NN;
    for (int i = 0; i < 6; i++) pj.hres[i] = nullptr;
    gemm128<<<dim3(gM, 6), 256>>>(pj, NN, 0, nullptr);

    // per-relation head transforms
    dim3 tgrid(NN / 4, 4, 2);
    transform_kernel<<<tgrid, 256>>>(ratt, rmsg);

    // --- fused score + softmax + aggregate (writes agg directly) ---
    attn_kernel<<<(2 * PAD) / 8, 256>>>(rpri);

    // --- batched output GEMMs with fused mean (0.5), bias, sigmoid skip ---
    GemmBatch og;
    og.A[0] = base + OFF_AGG;        og.W[0] = Wa;             og.bias[0] = ba;       og.C[0] = out;        og.hres[0] = h_a;
    og.A[1] = base + OFF_AGG + S_NN; og.W[1] = Wa + 128 * 128; og.bias[1] = ba + 128; og.C[1] = out + S_NN; og.hres[1] = h_b;
    for (int i = 2; i < 6; i++) { og.A[i] = nullptr; og.W[i] = nullptr; og.bias[i] = nullptr; og.C[i] = nullptr; og.hres[i] = nullptr; }
    gemm128<<<dim3(gM, 2), 256>>>(og, NN, 1, skip);
}